// round 14
// baseline (speedup 1.0000x reference)
#include <cuda_runtime.h>
#include <cstdint>

#define N_ROWS   100000
#define NBINS    512
#define BATCH    8192
#define KNN      16
#define COL_BLKS 64
#define CS_ROWS  (BATCH / COL_BLKS)     // 128 rows per colsum CTA
#define THREADS  512
#define TOTAL_BLKS (BATCH + COL_BLKS)
#define F_BLKS   8
#define STRIPS_PER_FCTA (COL_BLKS / F_BLKS)   // 8
#define WROWS_PER_FCTA  (BATCH / F_BLKS)      // 1024
#define ROW_BYTES (NBINS * 4)                 // 2048

// Scratch (device allocs forbidden). Fully rewritten every launch.
__device__ float        g_wpart[BATCH];
__device__ float        g_bpart[COL_BLKS * NBINS];
__device__ float        g_cpart[F_BLKS * NBINS];
__device__ double       g_wsum2[F_BLKS];
__device__ unsigned int g_count = 0;

__device__ __forceinline__ uint32_t smem_u32(const void* p) {
    uint32_t a;
    asm("{ .reg .u64 t; cvta.to.shared.u64 t, %1; cvt.u32.u64 %0, t; }"
        : "=r"(a) : "l"(p));
    return a;
}

// ---------------------------------------------------------------------------
// Kernel A: fused grid. bid<64: column-sum strip. bid>=64: pair row i with
// BULK-ASYNC gathers: 17 x 2KB rows (base + 16 neighbors) land in SMEM via
// cp.async.bulk + mbarrier — no gather registers, deep in-flight byte count.
// ---------------------------------------------------------------------------
__global__ __launch_bounds__(THREADS) void main_kernel(
    const float* __restrict__ outputs,
    const float* __restrict__ y,
    const float* __restrict__ weights,
    float* __restrict__ out_boost)   // -> d_out + 3
{
    cudaTriggerProgrammaticLaunchCompletion();

    const int bid = blockIdx.x;
    const int tid = threadIdx.x;

    if (bid < COL_BLKS) {
        // Column-sum strip: thread t owns bin t over 128 rows (coalesced).
        const float* p = outputs + (size_t)bid * CS_ROWS * NBINS + tid;
        float s = 0.f;
#pragma unroll
        for (int rb = 0; rb < CS_ROWS; rb += 8) {
            float t8[8];
#pragma unroll
            for (int r = 0; r < 8; r++) t8[r] = p[(size_t)(rb + r) * NBINS];
#pragma unroll
            for (int r = 0; r < 8; r++) s += t8[r];
        }
        g_bpart[bid * NBINS + tid] = s;
        return;
    }

    // ---- Pair CTA: SMEM-staged bulk gathers.
    __shared__ __align__(128) float    s_rows[17][NBINS];  // [0]=base, [1+j]=nbr j
    __shared__ __align__(8)   uint64_t s_mbar;
    __shared__ float                   s_add[KNN];

    const int i    = bid - COL_BLKS;
    const int warp = tid >> 5;
    const int lane = tid & 31;
    const uint32_t mbar = smem_u32(&s_mbar);

    if (tid == 0)
        asm volatile("mbarrier.init.shared.b64 [%0], %1;" :: "r"(mbar), "r"(16) : "memory");
    __syncthreads();

    // Warp j's lane 0: announce tx + issue bulk copy of neighbor row j.
    // Warp 0 additionally copies the base row.
    if (lane == 0) {
        const int nn = (int)__ldg(&y[i * KNN + warp]);
        const uint32_t bytes = (warp == 0) ? 2 * ROW_BYTES : ROW_BYTES;
        asm volatile("mbarrier.arrive.expect_tx.shared.b64 _, [%0], %1;"
                     :: "r"(mbar), "r"(bytes) : "memory");
        const void* src = (const void*)(outputs + (size_t)nn * NBINS);
        uint32_t dst = smem_u32(&s_rows[1 + warp][0]);
        asm volatile(
            "cp.async.bulk.shared::cluster.global.mbarrier::complete_tx::bytes "
            "[%0], [%1], %2, [%3];"
            :: "r"(dst), "l"(src), "r"((uint32_t)ROW_BYTES), "r"(mbar) : "memory");
        if (warp == 0) {
            const void* bsrc = (const void*)(outputs + (size_t)i * NBINS);
            uint32_t bdst = smem_u32(&s_rows[0][0]);
            asm volatile(
                "cp.async.bulk.shared::cluster.global.mbarrier::complete_tx::bytes "
                "[%0], [%1], %2, [%3];"
                :: "r"(bdst), "l"(bsrc), "r"((uint32_t)ROW_BYTES), "r"(mbar) : "memory");
        }
    }

    // All threads wait for all 17 rows (parity 0; barrier fresh each launch).
    {
        uint32_t done;
        asm volatile(
            "{\n\t.reg .pred p;\n\t"
            "mbarrier.try_wait.parity.acquire.cta.shared::cta.b64 p, [%1], %2;\n\t"
            "selp.b32 %0, 1, 0, p;\n\t}"
            : "=r"(done) : "r"(mbar), "r"(0) : "memory");
        if (!done) {
            asm volatile(
                "{\n\t.reg .pred P1;\n\t"
                "WL_%=:\n\t"
                "mbarrier.try_wait.parity.acquire.cta.shared::cta.b64 P1, [%0], %1, 0x989680;\n\t"
                "@P1 bra.uni WD_%=;\n\t"
                "bra.uni WL_%=;\n\t"
                "WD_%=:\n\t}"
                :: "r"(mbar), "r"(0) : "memory");
        }
    }

    // Compute: warp j reduces max over bins of (base + nbr_j), all from SMEM.
    const float4* nb = reinterpret_cast<const float4*>(&s_rows[1 + warp][0]);
    const float4* bs = reinterpret_cast<const float4*>(&s_rows[0][0]);

    float4 n0 = nb[lane],      n1 = nb[32 + lane], n2 = nb[64 + lane], n3 = nb[96 + lane];
    float4 b0 = bs[lane],      b1 = bs[32 + lane], b2 = bs[64 + lane], b3 = bs[96 + lane];

    float m0 = fmaxf(fmaxf(b0.x + n0.x, b0.y + n0.y), fmaxf(b0.z + n0.z, b0.w + n0.w));
    float m1 = fmaxf(fmaxf(b1.x + n1.x, b1.y + n1.y), fmaxf(b1.z + n1.z, b1.w + n1.w));
    float m2 = fmaxf(fmaxf(b2.x + n2.x, b2.y + n2.y), fmaxf(b2.z + n2.z, b2.w + n2.w));
    float m3 = fmaxf(fmaxf(b3.x + n3.x, b3.y + n3.y), fmaxf(b3.z + n3.z, b3.w + n3.w));
    float m  = fmaxf(fmaxf(m0, m1), fmaxf(m2, m3));

#pragma unroll
    for (int o = 16; o; o >>= 1)
        m = fmaxf(m, __shfl_xor_sync(0xffffffffu, m, o));
    if (lane == 0) s_add[warp] = m;
    __syncthreads();

    if (tid == 0) {
        float s = 0.f;
#pragma unroll
        for (int j = 0; j < KNN; j++) s += s_add[j];
        out_boost[i] = fmaxf((2.0f - s * (1.0f / KNN)) * 0.5f, 0.5f);
        g_wpart[i]   = s * weights[i];
    }
}

// ---------------------------------------------------------------------------
// Kernel B: 8-CTA PDL finalizer (proven).
// ---------------------------------------------------------------------------
__global__ __launch_bounds__(THREADS) void final_kernel(float* __restrict__ d_out)
{
    cudaGridDependencySynchronize();

    __shared__ unsigned s_ticket;
    __shared__ double   s_ws[16];
    __shared__ float    s_mx[16];
    __shared__ float    s_mn[16];

    const int c    = blockIdx.x;
    const int tid  = threadIdx.x;
    const int warp = tid >> 5;
    const int lane = tid & 31;

    {
        float s = 0.f;
        float t8[STRIPS_PER_FCTA];
#pragma unroll
        for (int k = 0; k < STRIPS_PER_FCTA; k++)
            t8[k] = g_bpart[(c * STRIPS_PER_FCTA + k) * NBINS + tid];
#pragma unroll
        for (int k = 0; k < STRIPS_PER_FCTA; k++) s += t8[k];
        g_cpart[c * NBINS + tid] = s;
    }
    {
        const float* w = g_wpart + c * WROWS_PER_FCTA;
        double ws = (double)w[tid] + (double)w[tid + THREADS];
#pragma unroll
        for (int o = 16; o; o >>= 1)
            ws += __shfl_xor_sync(0xffffffffu, ws, o);
        if (lane == 0) s_ws[warp] = ws;
        __syncthreads();
        if (tid == 0) {
            double t = 0.0;
#pragma unroll
            for (int wv = 0; wv < 16; wv++) t += s_ws[wv];
            g_wsum2[c] = t;
        }
    }

    if (tid == 0) {
        unsigned t;
        asm volatile("atom.add.release.gpu.global.u32 %0, [%1], 1;"
                     : "=r"(t) : "l"(&g_count) : "memory");
        s_ticket = t;
    }
    __syncthreads();
    if (s_ticket != F_BLKS - 1) return;

    asm volatile("fence.acq_rel.gpu;" ::: "memory");

    float col = 0.f;
    {
        float t8[F_BLKS];
#pragma unroll
        for (int b = 0; b < F_BLKS; b++) t8[b] = __ldcg(&g_cpart[b * NBINS + tid]);
#pragma unroll
        for (int b = 0; b < F_BLKS; b++) col += t8[b];
    }
    float mx = col, mn = col;
#pragma unroll
    for (int o = 16; o; o >>= 1) {
        mx = fmaxf(mx, __shfl_xor_sync(0xffffffffu, mx, o));
        mn = fminf(mn, __shfl_xor_sync(0xffffffffu, mn, o));
    }
    if (lane == 0) { s_mx[warp] = mx; s_mn[warp] = mn; }
    __syncthreads();

    if (warp == 0) {
        float fx = (lane < 16) ? s_mx[lane] : -1e30f;
        float fn = (lane < 16) ? s_mn[lane] :  1e30f;
#pragma unroll
        for (int o = 8; o; o >>= 1) {
            fx = fmaxf(fx, __shfl_xor_sync(0xffffffffu, fx, o));
            fn = fminf(fn, __shfl_xor_sync(0xffffffffu, fn, o));
        }
        if (lane == 0) {
            double ws = 0.0;
#pragma unroll
            for (int b = 0; b < F_BLKS; b++) ws += g_wsum2[b];

            float bspread  = fx - fn;
            float ratio    = bspread / ((float)N_ROWS / (float)NBINS);
            float add_mean = (float)(ws / (double)(BATCH * KNN));
            float d        = 2.0f - add_mean;
            d = d * d;
            d_out[0] = ratio + d;
            d_out[1] = d;
            d_out[2] = ratio;
            g_count  = 0;
        }
    }
}

// ---------------------------------------------------------------------------
extern "C" void kernel_launch(void* const* d_in, const int* in_sizes, int n_in,
                              void* d_out, int out_size)
{
    const float* outputs = (const float*)d_in[0];
    const float* y       = (const float*)d_in[1];
    const float* weights = (const float*)d_in[2];
    float* out = (float*)d_out;

    main_kernel<<<TOTAL_BLKS, THREADS>>>(outputs, y, weights, out + 3);

    cudaLaunchConfig_t cfg = {};
    cfg.gridDim  = dim3(F_BLKS, 1, 1);
    cfg.blockDim = dim3(THREADS, 1, 1);
    cudaLaunchAttribute attr[1];
    attr[0].id = cudaLaunchAttributeProgrammaticStreamSerialization;
    attr[0].val.programmaticStreamSerializationAllowed = 1;
    cfg.attrs    = attr;
    cfg.numAttrs = 1;
    cudaLaunchKernelEx(&cfg, final_kernel, out);
}

// round 15
// speedup vs baseline: 1.1941x; 1.1941x over previous
#include <cuda_runtime.h>

#define N_ROWS   100000
#define NBINS    512
#define BATCH    8192
#define KNN      16
#define COL_BLKS 64
#define CS_ROWS  (BATCH / COL_BLKS)     // 128 rows per colsum CTA
#define THREADS  512
#define PAIR_BLKS (BATCH / 2)           // 4096 CTAs, 2 batch rows each
#define TOTAL_BLKS (PAIR_BLKS + COL_BLKS)
#define F_BLKS   8
#define STRIPS_PER_FCTA (COL_BLKS / F_BLKS)   // 8
#define WROWS_PER_FCTA  (BATCH / F_BLKS)      // 1024

// Scratch (device allocs forbidden). Fully rewritten every launch.
__device__ float        g_wpart[BATCH];             // w[i] * sum_j add[i][j]
__device__ float        g_bpart[COL_BLKS * NBINS];  // per-strip column sums
__device__ float        g_cpart[F_BLKS * NBINS];    // finalizer partial col sums
__device__ double       g_wsum2[F_BLKS];            // finalizer partial weighted sums
__device__ unsigned int g_count = 0;                // 8-way ticket (finalizer only)

// ---------------------------------------------------------------------------
// Kernel A (PROVEN R13 shape, ~36us): fused grid, no cross-CTA sync.
//   bid < 64 : column-sum strip
//   bid >= 64: TWO batch rows; warp j gathers neighbor j of both rows ->
//              8 gather LDG.128 in flight per lane.
// ---------------------------------------------------------------------------
__global__ __launch_bounds__(THREADS) void main_kernel(
    const float* __restrict__ outputs,
    const float* __restrict__ y,
    const float* __restrict__ weights,
    float* __restrict__ out_boost)   // -> d_out + 3
{
    const int bid = blockIdx.x;
    const int tid = threadIdx.x;

    if (bid < COL_BLKS) {
        const float* p = outputs + (size_t)bid * CS_ROWS * NBINS + tid;
        float s = 0.f;
#pragma unroll
        for (int rb = 0; rb < CS_ROWS; rb += 8) {
            float t8[8];
#pragma unroll
            for (int r = 0; r < 8; r++) t8[r] = p[(size_t)(rb + r) * NBINS];
#pragma unroll
            for (int r = 0; r < 8; r++) s += t8[r];
        }
        g_bpart[bid * NBINS + tid] = s;
        return;
    }

    __shared__ float s_base0[NBINS];
    __shared__ float s_base1[NBINS];
    __shared__ float s_add0[KNN];
    __shared__ float s_add1[KNN];

    const int p    = bid - COL_BLKS;
    const int i0   = 2 * p;
    const int i1   = i0 + 1;
    const int warp = tid >> 5;
    const int lane = tid & 31;

    // Stage both base rows in SMEM (256 float4 total).
    {
        float4* s0 = reinterpret_cast<float4*>(s_base0);
        float4* s1 = reinterpret_cast<float4*>(s_base1);
        const float4* b0 = reinterpret_cast<const float4*>(outputs + (size_t)i0 * NBINS);
        const float4* b1 = reinterpret_cast<const float4*>(outputs + (size_t)i1 * NBINS);
        if (tid < 128)            s0[tid]       = b0[tid];
        else if (tid < 256)       s1[tid - 128] = b1[tid - 128];
    }

    // 8 independent gather LDG.128 per lane — all issued before the barrier.
    const int nn0 = (int)y[i0 * KNN + warp];
    const int nn1 = (int)y[i1 * KNN + warp];
    const float4* q0 = reinterpret_cast<const float4*>(outputs + (size_t)nn0 * NBINS);
    const float4* q1 = reinterpret_cast<const float4*>(outputs + (size_t)nn1 * NBINS);

    float4 a0 = q0[lane];
    float4 a1 = q0[32 + lane];
    float4 a2 = q0[64 + lane];
    float4 a3 = q0[96 + lane];
    float4 c0 = q1[lane];
    float4 c1 = q1[32 + lane];
    float4 c2 = q1[64 + lane];
    float4 c3 = q1[96 + lane];

    __syncthreads();   // base rows staged

    const float4* s0 = reinterpret_cast<const float4*>(s_base0);
    const float4* s1 = reinterpret_cast<const float4*>(s_base1);

    float ma, mb;
    {
        float4 b0 = s0[lane], b1 = s0[32 + lane], b2 = s0[64 + lane], b3 = s0[96 + lane];
        float m0 = fmaxf(fmaxf(b0.x + a0.x, b0.y + a0.y), fmaxf(b0.z + a0.z, b0.w + a0.w));
        float m1 = fmaxf(fmaxf(b1.x + a1.x, b1.y + a1.y), fmaxf(b1.z + a1.z, b1.w + a1.w));
        float m2 = fmaxf(fmaxf(b2.x + a2.x, b2.y + a2.y), fmaxf(b2.z + a2.z, b2.w + a2.w));
        float m3 = fmaxf(fmaxf(b3.x + a3.x, b3.y + a3.y), fmaxf(b3.z + a3.z, b3.w + a3.w));
        ma = fmaxf(fmaxf(m0, m1), fmaxf(m2, m3));
    }
    {
        float4 b0 = s1[lane], b1 = s1[32 + lane], b2 = s1[64 + lane], b3 = s1[96 + lane];
        float m0 = fmaxf(fmaxf(b0.x + c0.x, b0.y + c0.y), fmaxf(b0.z + c0.z, b0.w + c0.w));
        float m1 = fmaxf(fmaxf(b1.x + c1.x, b1.y + c1.y), fmaxf(b1.z + c1.z, b1.w + c1.w));
        float m2 = fmaxf(fmaxf(b2.x + c2.x, b2.y + c2.y), fmaxf(b2.z + c2.z, b2.w + c2.w));
        float m3 = fmaxf(fmaxf(b3.x + c3.x, b3.y + c3.y), fmaxf(b3.z + c3.z, b3.w + c3.w));
        mb = fmaxf(fmaxf(m0, m1), fmaxf(m2, m3));
    }

#pragma unroll
    for (int o = 16; o; o >>= 1) {
        ma = fmaxf(ma, __shfl_xor_sync(0xffffffffu, ma, o));
        mb = fmaxf(mb, __shfl_xor_sync(0xffffffffu, mb, o));
    }
    if (lane == 0) { s_add0[warp] = ma; s_add1[warp] = mb; }
    __syncthreads();

    if (tid == 0) {
        float sa = 0.f, sb = 0.f;
#pragma unroll
        for (int j = 0; j < KNN; j++) { sa += s_add0[j]; sb += s_add1[j]; }
        out_boost[i0] = fmaxf((2.0f - sa * (1.0f / KNN)) * 0.5f, 0.5f);
        out_boost[i1] = fmaxf((2.0f - sb * (1.0f / KNN)) * 0.5f, 0.5f);
        g_wpart[i0]   = sa * weights[i0];
        g_wpart[i1]   = sb * weights[i1];
    }
}

// ---------------------------------------------------------------------------
// Kernel B: plain (non-PDL) 8-CTA finalizer. Stream order provides the
// dependency on main_kernel; no grid-dep-sync, no PDL overhead.
// ---------------------------------------------------------------------------
__global__ __launch_bounds__(THREADS) void final_kernel(float* __restrict__ d_out)
{
    __shared__ unsigned s_ticket;
    __shared__ double   s_ws[16];
    __shared__ float    s_mx[16];
    __shared__ float    s_mn[16];

    const int c    = blockIdx.x;
    const int tid  = threadIdx.x;
    const int warp = tid >> 5;
    const int lane = tid & 31;

    // Partial column sums over this CTA's 8 strips.
    {
        float s = 0.f;
        float t8[STRIPS_PER_FCTA];
#pragma unroll
        for (int k = 0; k < STRIPS_PER_FCTA; k++)
            t8[k] = g_bpart[(c * STRIPS_PER_FCTA + k) * NBINS + tid];
#pragma unroll
        for (int k = 0; k < STRIPS_PER_FCTA; k++) s += t8[k];
        g_cpart[c * NBINS + tid] = s;
    }

    // Partial weighted sum over this CTA's 1024 g_wpart entries.
    {
        const float* w = g_wpart + c * WROWS_PER_FCTA;
        double ws = (double)w[tid] + (double)w[tid + THREADS];
#pragma unroll
        for (int o = 16; o; o >>= 1)
            ws += __shfl_xor_sync(0xffffffffu, ws, o);
        if (lane == 0) s_ws[warp] = ws;
        __syncthreads();
        if (tid == 0) {
            double t = 0.0;
#pragma unroll
            for (int wv = 0; wv < 16; wv++) t += s_ws[wv];
            g_wsum2[c] = t;
        }
    }

    // 8-way release ticket.
    if (tid == 0) {
        unsigned t;
        asm volatile("atom.add.release.gpu.global.u32 %0, [%1], 1;"
                     : "=r"(t) : "l"(&g_count) : "memory");
        s_ticket = t;
    }
    __syncthreads();
    if (s_ticket != F_BLKS - 1) return;

    asm volatile("fence.acq_rel.gpu;" ::: "memory");   // acquire partials

    float col = 0.f;
    {
        float t8[F_BLKS];
#pragma unroll
        for (int b = 0; b < F_BLKS; b++) t8[b] = __ldcg(&g_cpart[b * NBINS + tid]);
#pragma unroll
        for (int b = 0; b < F_BLKS; b++) col += t8[b];
    }
    float mx = col, mn = col;
#pragma unroll
    for (int o = 16; o; o >>= 1) {
        mx = fmaxf(mx, __shfl_xor_sync(0xffffffffu, mx, o));
        mn = fminf(mn, __shfl_xor_sync(0xffffffffu, mn, o));
    }
    if (lane == 0) { s_mx[warp] = mx; s_mn[warp] = mn; }
    __syncthreads();

    if (warp == 0) {
        float fx = (lane < 16) ? s_mx[lane] : -1e30f;
        float fn = (lane < 16) ? s_mn[lane] :  1e30f;
#pragma unroll
        for (int o = 8; o; o >>= 1) {
            fx = fmaxf(fx, __shfl_xor_sync(0xffffffffu, fx, o));
            fn = fminf(fn, __shfl_xor_sync(0xffffffffu, fn, o));
        }
        if (lane == 0) {
            double ws = 0.0;
#pragma unroll
            for (int b = 0; b < F_BLKS; b++) ws += g_wsum2[b];

            float bspread  = fx - fn;
            float ratio    = bspread / ((float)N_ROWS / (float)NBINS);
            float add_mean = (float)(ws / (double)(BATCH * KNN));
            float d        = 2.0f - add_mean;
            d = d * d;
            d_out[0] = ratio + d;   // cost
            d_out[1] = d;           // diff
            d_out[2] = ratio;       // b / target_b
            g_count  = 0;           // reset for next graph replay
        }
    }
}

// ---------------------------------------------------------------------------
extern "C" void kernel_launch(void* const* d_in, const int* in_sizes, int n_in,
                              void* d_out, int out_size)
{
    const float* outputs = (const float*)d_in[0];  // (100000, 512) f32
    const float* y       = (const float*)d_in[1];  // (8192, 16)   f32 indices
    const float* weights = (const float*)d_in[2];  // (8192,)      f32
    float* out = (float*)d_out;                    // [cost, diff, ratio, boost(8192)]

    main_kernel<<<TOTAL_BLKS, THREADS>>>(outputs, y, weights, out + 3);
    final_kernel<<<F_BLKS, THREADS>>>(out);
}